// round 3
// baseline (speedup 1.0000x reference)
#include <cuda_runtime.h>
#include <math.h>

// Problem dims
#define B_  256
#define S_  2048
#define I_  32
#define H_  18

// Scan pipeline config
#define CH      16               // timesteps per chunk
#define NC      (S_ / CH)        // 128 chunks
#define STRIDE  20               // padded row stride (floats) in smem rings

// Scratch: layer-2 hidden sequence [B, S, H] f32 (36 MB) — __device__ global,
// the sanctioned scratch mechanism (no allocations anywhere).
__device__ float g_h2[(long long)B_ * S_ * H_];

__device__ __forceinline__ float fast_tanh(float x) {
    // tanh(x) = 1 - 2/(exp(2x)+1); MUFU.EX2 + MUFU.RCP path, ~1e-6 accuracy.
    // x large positive -> e = inf -> 1 - 0 = 1. x large negative -> e = 0 -> -1.
    float e = __expf(2.0f * x);
    return 1.0f - __fdividef(2.0f, e + 1.0f);
}

// ---------------------------------------------------------------------------
// Kernel A: fused 3-layer RNN scan, chunk-pipelined across 4 warp roles.
//   role 0: xw0[t][j] = Wih0[j]·x_t + bih0[j] + bhh0[j]   (producer)
//   role 1: h0_t = tanh(xw0_t[j] + Whh0[j]·h0_{t-1})
//   role 2: h1_t = tanh(Wih1[j]·h0_t + b + Whh1[j]·h1_{t-1})
//   role 3: h2_t = tanh(Wih2[j]·h1_t + b + Whh2[j]·h2_{t-1}) -> g_h2
// Block = 2 batches x 4 warps. Grid = 128 (one wave on 148 SMs).
// ---------------------------------------------------------------------------
__global__ __launch_bounds__(256, 1)
void rnn_scan_kernel(const float* __restrict__ input,
                     const float* __restrict__ hidden,
                     const float* __restrict__ Wih0, const float* __restrict__ bih0,
                     const float* __restrict__ Whh0, const float* __restrict__ bhh0,
                     const float* __restrict__ Wih1, const float* __restrict__ bih1,
                     const float* __restrict__ Whh1, const float* __restrict__ bhh1,
                     const float* __restrict__ Wih2, const float* __restrict__ bih2,
                     const float* __restrict__ Whh2, const float* __restrict__ bhh2,
                     float* __restrict__ out, int write_hidden)
{
    __shared__ float s_x [2][CH][I_];            // x staging (role0 private per superstep)
    __shared__ float s_xw[2][2][CH][STRIDE];     // role0 -> role1 ring
    __shared__ float s_h0[2][2][CH][STRIDE];     // role1 -> role2 ring
    __shared__ float s_h1[2][2][CH][STRIDE];     // role2 -> role3 ring

    const int tid  = threadIdx.x;
    const int wid  = tid >> 5;
    const int lane = tid & 31;
    const int bi   = wid >> 2;                   // batch-in-block (0/1)
    // Mirror roles between the two batches so wid%4 SMSP pairing balances
    // heavy (roles 2/3) with light (roles 0/1) warps.
    const int role = (bi == 0) ? (wid & 3) : (3 - (wid & 3));
    const int b    = blockIdx.x * 2 + bi;
    const int jj   = (lane < H_) ? lane : 0;     // clamped row index
    const bool act = (lane < H_);

    float wA[I_];    // input-transform weight row (32 for role0, 18 for roles 2/3)
    float wB[H_];    // recurrent weight row
    float bsum = 0.f;
    float h    = 0.f;

    if (role == 0) {
        #pragma unroll
        for (int k = 0; k < I_; ++k) wA[k] = __ldg(&Wih0[jj * I_ + k]);
        bsum = __ldg(&bih0[jj]) + __ldg(&bhh0[jj]);
    } else if (role == 1) {
        #pragma unroll
        for (int k = 0; k < H_; ++k) wB[k] = __ldg(&Whh0[jj * H_ + k]);
        h = __ldg(&hidden[0 * B_ * H_ + b * H_ + jj]);
    } else if (role == 2) {
        #pragma unroll
        for (int k = 0; k < H_; ++k) {
            wA[k] = __ldg(&Wih1[jj * H_ + k]);
            wB[k] = __ldg(&Whh1[jj * H_ + k]);
        }
        bsum = __ldg(&bih1[jj]) + __ldg(&bhh1[jj]);
        h = __ldg(&hidden[1 * B_ * H_ + b * H_ + jj]);
    } else {
        #pragma unroll
        for (int k = 0; k < H_; ++k) {
            wA[k] = __ldg(&Wih2[jj * H_ + k]);
            wB[k] = __ldg(&Whh2[jj * H_ + k]);
        }
        bsum = __ldg(&bih2[jj]) + __ldg(&bhh2[jj]);
        h = __ldg(&hidden[2 * B_ * H_ + b * H_ + jj]);
    }

    // Superstep pipeline: role p processes chunk c = ss - p.
    // Producers write ring slot c&1; consumers (1 superstep behind) read the
    // other slot. One __syncthreads per superstep orders everything.
    for (int ss = 0; ss < NC + 3; ++ss) {
        const int c = ss - role;
        if (c >= 0 && c < NC) {
            const int t0   = c * CH;
            const int slot = c & 1;
            if (role == 0) {
                // Stage x chunk [CH,32] coalesced (float4), then compute xw0.
                const float4* xg = (const float4*)(input + ((size_t)b * S_ + t0) * I_);
                float4* xs = (float4*)&s_x[bi][0][0];
                #pragma unroll
                for (int i = 0; i < (CH * I_ / 4) / 32; ++i)
                    xs[lane + i * 32] = __ldg(&xg[lane + i * 32]);
                __syncwarp();
                for (int t = 0; t < CH; ++t) {
                    const float* xt = s_x[bi][t];
                    float a0 = bsum, a1 = 0.f, a2 = 0.f, a3 = 0.f;
                    #pragma unroll
                    for (int k = 0; k < 8; ++k) {
                        a0 = fmaf(wA[k],      xt[k],      a0);
                        a1 = fmaf(wA[k + 8],  xt[k + 8],  a1);
                        a2 = fmaf(wA[k + 16], xt[k + 16], a2);
                        a3 = fmaf(wA[k + 24], xt[k + 24], a3);
                    }
                    float acc = (a0 + a1) + (a2 + a3);
                    if (act) s_xw[bi][slot][t][lane] = acc;
                }
            } else if (role == 1) {
                for (int t = 0; t < CH; ++t) {
                    float pre = s_xw[bi][slot][t][jj];
                    float r0 = 0.f, r1 = 0.f, r2 = 0.f;
                    #pragma unroll
                    for (int k = 0; k < 6; ++k) {
                        r0 = fmaf(wB[k],      __shfl_sync(0xffffffffu, h, k),      r0);
                        r1 = fmaf(wB[k + 6],  __shfl_sync(0xffffffffu, h, k + 6),  r1);
                        r2 = fmaf(wB[k + 12], __shfl_sync(0xffffffffu, h, k + 12), r2);
                    }
                    h = fast_tanh(pre + ((r0 + r1) + r2));
                    if (act) s_h0[bi][slot][t][lane] = h;
                }
            } else if (role == 2) {
                for (int t = 0; t < CH; ++t) {
                    const float* hv = s_h0[bi][slot][t];
                    float p0 = bsum, p1 = 0.f;
                    #pragma unroll
                    for (int k = 0; k < 9; ++k) {
                        p0 = fmaf(wA[k],     hv[k],     p0);
                        p1 = fmaf(wA[k + 9], hv[k + 9], p1);
                    }
                    float r0 = 0.f, r1 = 0.f, r2 = 0.f;
                    #pragma unroll
                    for (int k = 0; k < 6; ++k) {
                        r0 = fmaf(wB[k],      __shfl_sync(0xffffffffu, h, k),      r0);
                        r1 = fmaf(wB[k + 6],  __shfl_sync(0xffffffffu, h, k + 6),  r1);
                        r2 = fmaf(wB[k + 12], __shfl_sync(0xffffffffu, h, k + 12), r2);
                    }
                    h = fast_tanh((p0 + p1) + ((r0 + r1) + r2));
                    if (act) s_h1[bi][slot][t][lane] = h;
                }
            } else { // role 3
                float* hout = g_h2 + ((size_t)b * S_ + t0) * H_;
                for (int t = 0; t < CH; ++t) {
                    const float* hv = s_h1[bi][slot][t];
                    float p0 = bsum, p1 = 0.f;
                    #pragma unroll
                    for (int k = 0; k < 9; ++k) {
                        p0 = fmaf(wA[k],     hv[k],     p0);
                        p1 = fmaf(wA[k + 9], hv[k + 9], p1);
                    }
                    float r0 = 0.f, r1 = 0.f, r2 = 0.f;
                    #pragma unroll
                    for (int k = 0; k < 6; ++k) {
                        r0 = fmaf(wB[k],      __shfl_sync(0xffffffffu, h, k),      r0);
                        r1 = fmaf(wB[k + 6],  __shfl_sync(0xffffffffu, h, k + 6),  r1);
                        r2 = fmaf(wB[k + 12], __shfl_sync(0xffffffffu, h, k + 12), r2);
                    }
                    h = fast_tanh((p0 + p1) + ((r0 + r1) + r2));
                    if (act) hout[t * H_ + lane] = h;
                }
            }
        }
        __syncthreads();
    }

    // Final hidden states: out[B*S + l*B*H + b*H + j]
    if (write_hidden && role >= 1 && act) {
        out[(size_t)B_ * S_ + (size_t)(role - 1) * B_ * H_ + b * H_ + lane] = h;
    }
}

// ---------------------------------------------------------------------------
// Kernel B: MLP head, one thread per (b,t) row. Weights staged to smem
// (warp-uniform broadcast reads).
// ---------------------------------------------------------------------------
__global__ __launch_bounds__(256)
void mlp_head_kernel(const float* __restrict__ W1, const float* __restrict__ b1,
                     const float* __restrict__ W2, const float* __restrict__ b2,
                     const float* __restrict__ W3, const float* __restrict__ b3,
                     const float* __restrict__ W4, const float* __restrict__ b4,
                     const float* __restrict__ W5, const float* __restrict__ b5,
                     const float* __restrict__ W6, const float* __restrict__ b6,
                     float* __restrict__ out)
{
    __shared__ float sW1[324], sW2[180], sW3[80], sW4[32], sW5[8], sW6[2];
    __shared__ float sb1[18], sb2[10], sb3[8], sb4[4], sb5[2], sb6[1];

    const int tid = threadIdx.x;
    for (int i = tid; i < 324; i += 256) sW1[i] = W1[i];
    if (tid < 180) sW2[tid] = W2[tid];
    if (tid < 80)  sW3[tid] = W3[tid];
    if (tid < 32)  sW4[tid] = W4[tid];
    if (tid < 18)  sb1[tid] = b1[tid];
    if (tid < 10)  sb2[tid] = b2[tid];
    if (tid < 8)  { sW5[tid] = W5[tid]; sb3[tid] = b3[tid]; }
    if (tid < 4)   sb4[tid] = b4[tid];
    if (tid < 2)  { sW6[tid] = W6[tid]; sb5[tid] = b5[tid]; }
    if (tid == 0)  sb6[0] = b6[0];
    __syncthreads();

    const size_t idx = (size_t)blockIdx.x * 256 + tid;
    if (idx >= (size_t)B_ * S_) return;

    float a0[18];
    const float2* hp = (const float2*)(g_h2 + idx * H_);  // 72B rows: float2-aligned
    #pragma unroll
    for (int i = 0; i < 9; ++i) {
        float2 v = __ldg(&hp[i]);
        a0[2 * i] = v.x; a0[2 * i + 1] = v.y;
    }

    float a1[18];
    #pragma unroll
    for (int j = 0; j < 18; ++j) {
        float s = sb1[j];
        #pragma unroll
        for (int k = 0; k < 18; ++k) s = fmaf(a0[k], sW1[j * 18 + k], s);
        a1[j] = fmaxf(s, 0.f);
    }
    float a2[10];
    #pragma unroll
    for (int j = 0; j < 10; ++j) {
        float s = sb2[j];
        #pragma unroll
        for (int k = 0; k < 18; ++k) s = fmaf(a1[k], sW2[j * 18 + k], s);
        a2[j] = fmaxf(s, 0.f);
    }
    float a3[8];
    #pragma unroll
    for (int j = 0; j < 8; ++j) {
        float s = sb3[j];
        #pragma unroll
        for (int k = 0; k < 10; ++k) s = fmaf(a2[k], sW3[j * 10 + k], s);
        a3[j] = fmaxf(s, 0.f);
    }
    float a4[4];
    #pragma unroll
    for (int j = 0; j < 4; ++j) {
        float s = sb4[j];
        #pragma unroll
        for (int k = 0; k < 8; ++k) s = fmaf(a3[k], sW4[j * 8 + k], s);
        a4[j] = fmaxf(s, 0.f);
    }
    float a5[2];
    #pragma unroll
    for (int j = 0; j < 2; ++j) {
        float s = sb5[j];
        #pragma unroll
        for (int k = 0; k < 4; ++k) s = fmaf(a4[k], sW5[j * 4 + k], s);
        a5[j] = fmaxf(s, 0.f);
    }
    float o = fmaf(a5[0], sW6[0], fmaf(a5[1], sW6[1], sb6[0]));
    out[idx] = o;
}

// ---------------------------------------------------------------------------
// Launch
// ---------------------------------------------------------------------------
extern "C" void kernel_launch(void* const* d_in, const int* in_sizes, int n_in,
                              void* d_out, int out_size)
{
    const float* input  = (const float*)d_in[0];
    const float* hidden = (const float*)d_in[1];
    const float* Wih0 = (const float*)d_in[2];
    const float* bih0 = (const float*)d_in[3];
    const float* Whh0 = (const float*)d_in[4];
    const float* bhh0 = (const float*)d_in[5];
    const float* Wih1 = (const float*)d_in[6];
    const float* bih1 = (const float*)d_in[7];
    const float* Whh1 = (const float*)d_in[8];
    const float* bhh1 = (const float*)d_in[9];
    const float* Wih2 = (const float*)d_in[10];
    const float* bih2 = (const float*)d_in[11];
    const float* Whh2 = (const float*)d_in[12];
    const float* bhh2 = (const float*)d_in[13];
    const float* W1 = (const float*)d_in[14];
    const float* b1 = (const float*)d_in[15];
    const float* W2 = (const float*)d_in[16];
    const float* b2 = (const float*)d_in[17];
    const float* W3 = (const float*)d_in[18];
    const float* b3 = (const float*)d_in[19];
    const float* W4 = (const float*)d_in[20];
    const float* b4 = (const float*)d_in[21];
    const float* W5 = (const float*)d_in[22];
    const float* b5 = (const float*)d_in[23];
    const float* W6 = (const float*)d_in[24];
    const float* b6 = (const float*)d_in[25];

    float* out = (float*)d_out;
    const int write_hidden = (out_size >= B_ * S_ + 3 * B_ * H_) ? 1 : 0;

    rnn_scan_kernel<<<B_ / 2, 256>>>(input, hidden,
                                     Wih0, bih0, Whh0, bhh0,
                                     Wih1, bih1, Whh1, bhh1,
                                     Wih2, bih2, Whh2, bhh2,
                                     out, write_hidden);

    mlp_head_kernel<<<(B_ * S_) / 256, 256>>>(W1, b1, W2, b2, W3, b3,
                                              W4, b4, W5, b5, W6, b6, out);
}

// round 4
// speedup vs baseline: 1.3176x; 1.3176x over previous
#include <cuda_runtime.h>
#include <math.h>

typedef unsigned long long u64;

// Problem dims
#define B_  256
#define S_  2048
#define I_  32
#define H_  18

// Scan pipeline config
#define CH      16               // timesteps per chunk
#define NC      (S_ / CH)        // 128 chunks
#define RS2     10               // row stride in u64 (=20 floats)

// Scratch: layer-2 hidden sequence [B, S, H] f32 (36 MB).
__device__ float g_h2[(size_t)B_ * S_ * H_];

// ---------------- packed f32x2 helpers (Blackwell FFMA2 path) ----------------
__device__ __forceinline__ void fma2(u64& d, u64 a, u64 b) {
    asm("fma.rn.f32x2 %0, %1, %2, %0;" : "+l"(d) : "l"(a), "l"(b));
}
__device__ __forceinline__ u64 add2(u64 a, u64 b) {
    u64 d; asm("add.rn.f32x2 %0, %1, %2;" : "=l"(d) : "l"(a), "l"(b)); return d;
}
__device__ __forceinline__ float hsum2(u64 a) {
    float x, y; asm("mov.b64 {%0, %1}, %2;" : "=f"(x), "=f"(y) : "l"(a));
    return x + y;
}
__device__ __forceinline__ u64 pack2(float x, float y) {
    u64 d; asm("mov.b64 %0, {%1, %2};" : "=l"(d) : "f"(x), "f"(y)); return d;
}

__device__ __forceinline__ float fast_tanh(float x) {
    // tanh(x) = 1 - 2/(exp(2x)+1); EX2+RCP path, ~1e-6 accuracy (validated 2e-7 rel).
    float e = __expf(2.0f * x);
    return 1.0f - __fdividef(2.0f, e + 1.0f);
}

// ---------------------------------------------------------------------------
// Kernel A: fused 3-layer RNN scan, chunk-pipelined across 4 warp roles.
// Shuffle-free: recurrent dot reads previous h row back from smem as f32x2
// pairs (broadcast LDS.64); all dots use fma.rn.f32x2.
// Block = 2 batches x 4 warps. Grid = 128 (one wave).
// ---------------------------------------------------------------------------
__global__ __launch_bounds__(256, 1)
void rnn_scan_kernel(const float* __restrict__ input,
                     const float* __restrict__ hidden,
                     const float* __restrict__ Wih0, const float* __restrict__ bih0,
                     const float* __restrict__ Whh0, const float* __restrict__ bhh0,
                     const float* __restrict__ Wih1, const float* __restrict__ bih1,
                     const float* __restrict__ Whh1, const float* __restrict__ bhh1,
                     const float* __restrict__ Wih2, const float* __restrict__ bih2,
                     const float* __restrict__ Whh2, const float* __restrict__ bhh2,
                     float* __restrict__ out, int write_hidden)
{
    __shared__ float4 s_x [2][CH][8];           // x staging (within-superstep)
    __shared__ u64    s_xw[2][2][CH][RS2];      // role0 -> role1 ring
    __shared__ u64    s_h0[2][2][CH][RS2];      // role1 -> role2 ring (+ self)
    __shared__ u64    s_h1[2][2][CH][RS2];      // role2 -> role3 ring (+ self)
    __shared__ u64    s_h2[2][2][CH][RS2];      // role3 self ring

    const int tid  = threadIdx.x;
    const int wid  = tid >> 5;
    const int lane = tid & 31;
    const int bi   = wid >> 2;
    const int role = bi ? (3 - (wid & 3)) : (wid & 3);  // mirror for SMSP balance
    const int b    = blockIdx.x * 2 + bi;
    const int jj   = (lane < H_) ? lane : 0;
    const bool act = (lane < H_);

    u64 wA[16];      // role0 input weights (16 pairs)
    u64 wP[9];       // roles 2/3 input-transform weight pairs
    u64 wR[9];       // roles 1-3 recurrent weight pairs
    float bsum = 0.f, h = 0.f;

    if (role == 0) {
        const u64* w = (const u64*)(Wih0 + jj * I_);
        #pragma unroll
        for (int m = 0; m < 16; ++m) wA[m] = __ldg(&w[m]);
        bsum = __ldg(&bih0[jj]) + __ldg(&bhh0[jj]);
    } else if (role == 1) {
        const u64* w = (const u64*)(Whh0 + jj * H_);
        #pragma unroll
        for (int m = 0; m < 9; ++m) wR[m] = __ldg(&w[m]);
        h = __ldg(&hidden[0 * B_ * H_ + b * H_ + jj]);
        if (act) ((float*)&s_h0[bi][1][CH - 1][0])[lane] = h;   // seed c=-1
    } else if (role == 2) {
        const u64* wp = (const u64*)(Wih1 + jj * H_);
        const u64* wr = (const u64*)(Whh1 + jj * H_);
        #pragma unroll
        for (int m = 0; m < 9; ++m) { wP[m] = __ldg(&wp[m]); wR[m] = __ldg(&wr[m]); }
        bsum = __ldg(&bih1[jj]) + __ldg(&bhh1[jj]);
        h = __ldg(&hidden[1 * B_ * H_ + b * H_ + jj]);
        if (act) ((float*)&s_h1[bi][1][CH - 1][0])[lane] = h;
    } else {
        const u64* wp = (const u64*)(Wih2 + jj * H_);
        const u64* wr = (const u64*)(Whh2 + jj * H_);
        #pragma unroll
        for (int m = 0; m < 9; ++m) { wP[m] = __ldg(&wp[m]); wR[m] = __ldg(&wr[m]); }
        bsum = __ldg(&bih2[jj]) + __ldg(&bhh2[jj]);
        h = __ldg(&hidden[2 * B_ * H_ + b * H_ + jj]);
        if (act) ((float*)&s_h2[bi][1][CH - 1][0])[lane] = h;
    }
    const u64 binit = pack2(bsum, 0.f);

    for (int ss = 0; ss < NC + 3; ++ss) {
        const int c = ss - role;
        if (c >= 0 && c < NC) {
            const int slot = c & 1;
            const int t0   = c * CH;
            if (role == 0) {
                // Stage x chunk [16,32] coalesced (float4), then 16 FFMA2 / step.
                const float4* xg = (const float4*)(input + ((size_t)b * S_ + t0) * I_);
                float4* xs = (float4*)&s_x[bi][0][0];
                #pragma unroll
                for (int i = 0; i < 4; ++i) xs[lane + 32 * i] = __ldg(&xg[lane + 32 * i]);
                __syncwarp();
                #pragma unroll 4
                for (int t = 0; t < CH; ++t) {
                    const u64* xt = (const u64*)&s_x[bi][t][0];
                    u64 a0 = binit, a1 = 0ull, a2 = 0ull, a3 = 0ull;
                    #pragma unroll
                    for (int m = 0; m < 4; ++m) {
                        fma2(a0, wA[m],      xt[m]);
                        fma2(a1, wA[m + 4],  xt[m + 4]);
                        fma2(a2, wA[m + 8],  xt[m + 8]);
                        fma2(a3, wA[m + 12], xt[m + 12]);
                    }
                    a0 = add2(a0, a1); a2 = add2(a2, a3); a0 = add2(a0, a2);
                    if (act) ((float*)&s_xw[bi][slot][t][0])[lane] = hsum2(a0);
                }
            } else if (role == 1) {
                const u64* hp = &s_h0[bi][slot ^ 1][CH - 1][0];
                #pragma unroll 4
                for (int t = 0; t < CH; ++t) {
                    float pre = ((const float*)&s_xw[bi][slot][t][0])[jj];
                    u64 a0 = pack2(pre, 0.f), a1 = 0ull, a2 = 0ull;
                    fma2(a0, wR[0], hp[0]); fma2(a1, wR[1], hp[1]); fma2(a2, wR[2], hp[2]);
                    fma2(a0, wR[3], hp[3]); fma2(a1, wR[4], hp[4]); fma2(a2, wR[5], hp[5]);
                    fma2(a0, wR[6], hp[6]); fma2(a1, wR[7], hp[7]); fma2(a2, wR[8], hp[8]);
                    h = fast_tanh(hsum2(add2(add2(a0, a1), a2)));
                    if (act) ((float*)&s_h0[bi][slot][t][0])[lane] = h;
                    hp = &s_h0[bi][slot][t][0];
                    __syncwarp();
                }
            } else if (role == 2) {
                const u64* hp = &s_h1[bi][slot ^ 1][CH - 1][0];
                #pragma unroll 4
                for (int t = 0; t < CH; ++t) {
                    const u64* pv = &s_h0[bi][slot][t][0];   // producer row (ready)
                    u64 a0 = binit, a1 = 0ull, a2 = 0ull;
                    fma2(a0, wP[0], pv[0]); fma2(a1, wP[1], pv[1]); fma2(a2, wP[2], pv[2]);
                    fma2(a0, wP[3], pv[3]); fma2(a1, wP[4], pv[4]); fma2(a2, wP[5], pv[5]);
                    fma2(a0, wP[6], pv[6]); fma2(a1, wP[7], pv[7]); fma2(a2, wP[8], pv[8]);
                    fma2(a0, wR[0], hp[0]); fma2(a1, wR[1], hp[1]); fma2(a2, wR[2], hp[2]);
                    fma2(a0, wR[3], hp[3]); fma2(a1, wR[4], hp[4]); fma2(a2, wR[5], hp[5]);
                    fma2(a0, wR[6], hp[6]); fma2(a1, wR[7], hp[7]); fma2(a2, wR[8], hp[8]);
                    h = fast_tanh(hsum2(add2(add2(a0, a1), a2)));
                    if (act) ((float*)&s_h1[bi][slot][t][0])[lane] = h;
                    hp = &s_h1[bi][slot][t][0];
                    __syncwarp();
                }
            } else { // role 3
                const u64* hp = &s_h2[bi][slot ^ 1][CH - 1][0];
                float* go = g_h2 + ((size_t)b * S_ + t0) * H_;
                #pragma unroll 4
                for (int t = 0; t < CH; ++t) {
                    const u64* pv = &s_h1[bi][slot][t][0];
                    u64 a0 = binit, a1 = 0ull, a2 = 0ull;
                    fma2(a0, wP[0], pv[0]); fma2(a1, wP[1], pv[1]); fma2(a2, wP[2], pv[2]);
                    fma2(a0, wP[3], pv[3]); fma2(a1, wP[4], pv[4]); fma2(a2, wP[5], pv[5]);
                    fma2(a0, wP[6], pv[6]); fma2(a1, wP[7], pv[7]); fma2(a2, wP[8], pv[8]);
                    fma2(a0, wR[0], hp[0]); fma2(a1, wR[1], hp[1]); fma2(a2, wR[2], hp[2]);
                    fma2(a0, wR[3], hp[3]); fma2(a1, wR[4], hp[4]); fma2(a2, wR[5], hp[5]);
                    fma2(a0, wR[6], hp[6]); fma2(a1, wR[7], hp[7]); fma2(a2, wR[8], hp[8]);
                    h = fast_tanh(hsum2(add2(add2(a0, a1), a2)));
                    if (act) {
                        ((float*)&s_h2[bi][slot][t][0])[lane] = h;
                        go[t * H_ + lane] = h;
                    }
                    hp = &s_h2[bi][slot][t][0];
                    __syncwarp();
                }
            }
        }
        __syncthreads();
    }

    if (write_hidden && role >= 1 && act)
        out[(size_t)B_ * S_ + (size_t)(role - 1) * B_ * H_ + b * H_ + lane] = h;
}

// ---------------------------------------------------------------------------
// Kernel B: MLP head, f32x2-packed, one thread per (b,t) row.
// ---------------------------------------------------------------------------
__global__ __launch_bounds__(256)
void mlp_head_kernel(const float* __restrict__ W1, const float* __restrict__ b1,
                     const float* __restrict__ W2, const float* __restrict__ b2,
                     const float* __restrict__ W3, const float* __restrict__ b3,
                     const float* __restrict__ W4, const float* __restrict__ b4,
                     const float* __restrict__ W5, const float* __restrict__ b5,
                     const float* __restrict__ W6, const float* __restrict__ b6,
                     float* __restrict__ out)
{
    __shared__ u64 sW1[162], sW2[90], sW3[40], sW4[16], sW5[4];
    __shared__ float sb1[18], sb2[10], sb3[8], sb4[4], sb5[2], sW6f[2], sb6f[1];

    const int tid = threadIdx.x;
    if (tid < 162) sW1[tid] = __ldg((const u64*)W1 + tid);
    if (tid < 90)  sW2[tid] = __ldg((const u64*)W2 + tid);
    if (tid < 40)  sW3[tid] = __ldg((const u64*)W3 + tid);
    if (tid < 16)  sW4[tid] = __ldg((const u64*)W4 + tid);
    if (tid < 4)  { sW5[tid] = __ldg((const u64*)W5 + tid); sb4[tid] = b4[tid]; }
    if (tid < 18)  sb1[tid] = b1[tid];
    if (tid < 10)  sb2[tid] = b2[tid];
    if (tid < 8)   sb3[tid] = b3[tid];
    if (tid < 2)  { sb5[tid] = b5[tid]; sW6f[tid] = W6[tid]; }
    if (tid == 0)  sb6f[0] = b6[0];
    __syncthreads();

    const size_t idx = (size_t)blockIdx.x * 256 + tid;
    if (idx >= (size_t)B_ * S_) return;

    u64 a0[9];
    const u64* hp = (const u64*)(g_h2 + idx * H_);   // 72B rows, 8B-aligned
    #pragma unroll
    for (int m = 0; m < 9; ++m) a0[m] = hp[m];

    float a1[18];
    #pragma unroll
    for (int j = 0; j < 18; ++j) {
        u64 acc = pack2(sb1[j], 0.f), accb = 0ull;
        #pragma unroll
        for (int m = 0; m < 9; ++m) fma2((m & 1) ? accb : acc, sW1[j * 9 + m], a0[m]);
        a1[j] = fmaxf(hsum2(add2(acc, accb)), 0.f);
    }
    u64 a1p[9];
    #pragma unroll
    for (int m = 0; m < 9; ++m) a1p[m] = pack2(a1[2 * m], a1[2 * m + 1]);

    float a2[10];
    #pragma unroll
    for (int j = 0; j < 10; ++j) {
        u64 acc = pack2(sb2[j], 0.f), accb = 0ull;
        #pragma unroll
        for (int m = 0; m < 9; ++m) fma2((m & 1) ? accb : acc, sW2[j * 9 + m], a1p[m]);
        a2[j] = fmaxf(hsum2(add2(acc, accb)), 0.f);
    }
    u64 a2p[5];
    #pragma unroll
    for (int m = 0; m < 5; ++m) a2p[m] = pack2(a2[2 * m], a2[2 * m + 1]);

    float a3[8];
    #pragma unroll
    for (int j = 0; j < 8; ++j) {
        u64 acc = pack2(sb3[j], 0.f), accb = 0ull;
        #pragma unroll
        for (int m = 0; m < 5; ++m) fma2((m & 1) ? accb : acc, sW3[j * 5 + m], a2p[m]);
        a3[j] = fmaxf(hsum2(add2(acc, accb)), 0.f);
    }
    u64 a3p[4];
    #pragma unroll
    for (int m = 0; m < 4; ++m) a3p[m] = pack2(a3[2 * m], a3[2 * m + 1]);

    float a4[4];
    #pragma unroll
    for (int j = 0; j < 4; ++j) {
        u64 acc = pack2(sb4[j], 0.f), accb = 0ull;
        #pragma unroll
        for (int m = 0; m < 4; ++m) fma2((m & 1) ? accb : acc, sW4[j * 4 + m], a3p[m]);
        a4[j] = fmaxf(hsum2(add2(acc, accb)), 0.f);
    }
    u64 a4p[2] = { pack2(a4[0], a4[1]), pack2(a4[2], a4[3]) };

    float a5[2];
    #pragma unroll
    for (int j = 0; j < 2; ++j) {
        u64 acc = pack2(sb5[j], 0.f);
        fma2(acc, sW5[j * 2 + 0], a4p[0]);
        fma2(acc, sW5[j * 2 + 1], a4p[1]);
        a5[j] = fmaxf(hsum2(acc), 0.f);
    }
    out[idx] = fmaf(a5[0], sW6f[0], fmaf(a5[1], sW6f[1], sb6f[0]));
}

// ---------------------------------------------------------------------------
// Launch
// ---------------------------------------------------------------------------
extern "C" void kernel_launch(void* const* d_in, const int* in_sizes, int n_in,
                              void* d_out, int out_size)
{
    const float* input  = (const float*)d_in[0];
    const float* hidden = (const float*)d_in[1];
    const float* Wih0 = (const float*)d_in[2];
    const float* bih0 = (const float*)d_in[3];
    const float* Whh0 = (const float*)d_in[4];
    const float* bhh0 = (const float*)d_in[5];
    const float* Wih1 = (const float*)d_in[6];
    const float* bih1 = (const float*)d_in[7];
    const float* Whh1 = (const float*)d_in[8];
    const float* bhh1 = (const float*)d_in[9];
    const float* Wih2 = (const float*)d_in[10];
    const float* bih2 = (const float*)d_in[11];
    const float* Whh2 = (const float*)d_in[12];
    const float* bhh2 = (const float*)d_in[13];
    const float* W1 = (const float*)d_in[14];
    const float* b1 = (const float*)d_in[15];
    const float* W2 = (const float*)d_in[16];
    const float* b2 = (const float*)d_in[17];
    const float* W3 = (const float*)d_in[18];
    const float* b3 = (const float*)d_in[19];
    const float* W4 = (const float*)d_in[20];
    const float* b4 = (const float*)d_in[21];
    const float* W5 = (const float*)d_in[22];
    const float* b5 = (const float*)d_in[23];
    const float* W6 = (const float*)d_in[24];
    const float* b6 = (const float*)d_in[25];

    float* out = (float*)d_out;
    const int write_hidden = (out_size >= B_ * S_ + 3 * B_ * H_) ? 1 : 0;

    rnn_scan_kernel<<<B_ / 2, 256>>>(input, hidden,
                                     Wih0, bih0, Whh0, bhh0,
                                     Wih1, bih1, Whh1, bhh1,
                                     Wih2, bih2, Whh2, bhh2,
                                     out, write_hidden);

    mlp_head_kernel<<<(B_ * S_) / 256, 256>>>(W1, b1, W2, b2, W3, b3,
                                              W4, b4, W5, b5, W6, b6, out);
}

// round 5
// speedup vs baseline: 1.6177x; 1.2277x over previous
#include <cuda_runtime.h>
#include <math.h>

typedef unsigned long long u64;
typedef unsigned int u32;

// Problem dims
#define B_  256
#define S_  2048
#define I_  32
#define H_  18

// Scan pipeline config
#define CH      16               // timesteps per chunk
#define NC      (S_ / CH)        // 128 chunks
#define RS2     10               // row stride in u64 (=20 floats = 80 bytes)
#define ROWB    80               // row stride bytes

// Scratch: layer-2 hidden sequence [B, S, H] f32 (36 MB).
__device__ float g_h2[(size_t)B_ * S_ * H_];

// ---------------- packed f32x2 helpers ----------------
__device__ __forceinline__ void fma2(u64& d, u64 a, u64 b) {
    asm("fma.rn.f32x2 %0, %1, %2, %0;" : "+l"(d) : "l"(a), "l"(b));
}
__device__ __forceinline__ u64 add2(u64 a, u64 b) {
    u64 d; asm("add.rn.f32x2 %0, %1, %2;" : "=l"(d) : "l"(a), "l"(b)); return d;
}
__device__ __forceinline__ float hsum2(u64 a) {
    float x, y; asm("mov.b64 {%0, %1}, %2;" : "=f"(x), "=f"(y) : "l"(a));
    return x + y;
}
__device__ __forceinline__ u64 pack2(float x, float y) {
    u64 d; asm("mov.b64 %0, {%1, %2};" : "=l"(d) : "f"(x), "f"(y)); return d;
}
__device__ __forceinline__ float tanh_fast(float x) {
    float r; asm("tanh.approx.f32 %0, %1;" : "=f"(r) : "f"(x)); return r;
}

// Ordered (volatile) shared ops for the per-step h handoff. All are
// asm volatile so ptxas keeps their mutual program order; the shared-memory
// pipeline serves same-warp ops in order, so no WARPSYNC is needed
// (inner loop is divergence-free).
__device__ __forceinline__ void sts_f32(u32 addr, float v) {
    asm volatile("st.shared.f32 [%0], %1;" :: "r"(addr), "f"(v));
}
__device__ __forceinline__ u64 lds_u64(u32 addr) {
    u64 v; asm volatile("ld.shared.b64 %0, [%1];" : "=l"(v) : "r"(addr)); return v;
}

// ---------------------------------------------------------------------------
// Kernel A: fused 3-layer RNN scan, chunk-pipelined across 4 warp roles.
// ---------------------------------------------------------------------------
__global__ __launch_bounds__(256, 1)
void rnn_scan_kernel(const float* __restrict__ input,
                     const float* __restrict__ hidden,
                     const float* __restrict__ Wih0, const float* __restrict__ bih0,
                     const float* __restrict__ Whh0, const float* __restrict__ bhh0,
                     const float* __restrict__ Wih1, const float* __restrict__ bih1,
                     const float* __restrict__ Whh1, const float* __restrict__ bhh1,
                     const float* __restrict__ Wih2, const float* __restrict__ bih2,
                     const float* __restrict__ Whh2, const float* __restrict__ bhh2,
                     float* __restrict__ out, int write_hidden)
{
    __shared__ float4 s_x [2][CH][8];           // x staging
    __shared__ u64    s_xw[2][2][CH][RS2];      // role0 -> role1
    __shared__ u64    s_h0[2][2][CH][RS2];      // role1 -> role2 (+ self)
    __shared__ u64    s_h1[2][2][CH][RS2];      // role2 -> role3 (+ self)
    __shared__ u64    s_h2[2][2][CH][RS2];      // role3 self

    const int tid  = threadIdx.x;
    const int wid  = tid >> 5;
    const int lane = tid & 31;
    const int bi   = wid >> 2;
    const int role = bi ? (3 - (wid & 3)) : (wid & 3);  // mirror for SMSP balance
    const int b    = blockIdx.x * 2 + bi;
    const int jj   = (lane < H_) ? lane : 0;            // clamped: dup lanes write
    const bool act = (lane < H_);                       // identical values -> benign

    u64 wA[16];      // role0 input weight pairs
    u64 wP[9];       // roles 2/3 input-transform weight pairs
    u64 wR[9];       // roles 1-3 recurrent weight pairs
    float bsum = 0.f, h = 0.f;

    if (role == 0) {
        const u64* w = (const u64*)(Wih0 + jj * I_);
        #pragma unroll
        for (int m = 0; m < 16; ++m) wA[m] = __ldg(&w[m]);
        bsum = __ldg(&bih0[jj]) + __ldg(&bhh0[jj]);
    } else if (role == 1) {
        const u64* w = (const u64*)(Whh0 + jj * H_);
        #pragma unroll
        for (int m = 0; m < 9; ++m) wR[m] = __ldg(&w[m]);
        h = __ldg(&hidden[0 * B_ * H_ + b * H_ + jj]);
        ((float*)&s_h0[bi][1][CH - 1][0])[jj] = h;       // seed c=-1
    } else if (role == 2) {
        const u64* wp = (const u64*)(Wih1 + jj * H_);
        const u64* wr = (const u64*)(Whh1 + jj * H_);
        #pragma unroll
        for (int m = 0; m < 9; ++m) { wP[m] = __ldg(&wp[m]); wR[m] = __ldg(&wr[m]); }
        bsum = __ldg(&bih1[jj]) + __ldg(&bhh1[jj]);
        h = __ldg(&hidden[1 * B_ * H_ + b * H_ + jj]);
        ((float*)&s_h1[bi][1][CH - 1][0])[jj] = h;
    } else {
        const u64* wp = (const u64*)(Wih2 + jj * H_);
        const u64* wr = (const u64*)(Whh2 + jj * H_);
        #pragma unroll
        for (int m = 0; m < 9; ++m) { wP[m] = __ldg(&wp[m]); wR[m] = __ldg(&wr[m]); }
        bsum = __ldg(&bih2[jj]) + __ldg(&bhh2[jj]);
        h = __ldg(&hidden[2 * B_ * H_ + b * H_ + jj]);
        ((float*)&s_h2[bi][1][CH - 1][0])[jj] = h;
    }
    const u64 binit = pack2(bsum, 0.f);

    // Shared-memory u32 bases for the self rings (asm addressing).
    u32 self_base = 0;
    if (role == 1) self_base = (u32)__cvta_generic_to_shared(&s_h0[bi][0][0][0]);
    if (role == 2) self_base = (u32)__cvta_generic_to_shared(&s_h1[bi][0][0][0]);
    if (role == 3) self_base = (u32)__cvta_generic_to_shared(&s_h2[bi][0][0][0]);

    for (int ss = 0; ss < NC + 3; ++ss) {
        const int c = ss - role;
        if (c >= 0 && c < NC) {
            const int slot = c & 1;
            const int t0   = c * CH;
            if (role == 0) {
                const float4* xg = (const float4*)(input + ((size_t)b * S_ + t0) * I_);
                float4* xs = (float4*)&s_x[bi][0][0];
                #pragma unroll
                for (int i = 0; i < 4; ++i) xs[lane + 32 * i] = __ldg(&xg[lane + 32 * i]);
                __syncwarp();
                #pragma unroll 4
                for (int t = 0; t < CH; ++t) {
                    const u64* xt = (const u64*)&s_x[bi][t][0];
                    u64 a0 = binit, a1 = 0ull, a2 = 0ull, a3 = 0ull;
                    #pragma unroll
                    for (int m = 0; m < 4; ++m) {
                        fma2(a0, wA[m],      xt[m]);
                        fma2(a1, wA[m + 4],  xt[m + 4]);
                        fma2(a2, wA[m + 8],  xt[m + 8]);
                        fma2(a3, wA[m + 12], xt[m + 12]);
                    }
                    a0 = add2(a0, a1); a2 = add2(a2, a3); a0 = add2(a0, a2);
                    ((float*)&s_xw[bi][slot][t][0])[jj] = hsum2(a0);
                }
            } else if (role == 1) {
                u32 hp  = self_base + ((slot ^ 1) * CH + CH - 1) * ROWB;
                u32 cur = self_base + (slot * CH) * ROWB;
                #pragma unroll 4
                for (int t = 0; t < CH; ++t) {
                    u64 v0 = lds_u64(hp),      v1 = lds_u64(hp + 8),  v2 = lds_u64(hp + 16);
                    u64 v3 = lds_u64(hp + 24), v4 = lds_u64(hp + 32), v5 = lds_u64(hp + 40);
                    u64 v6 = lds_u64(hp + 48), v7 = lds_u64(hp + 56), v8 = lds_u64(hp + 64);
                    float pre = ((const float*)&s_xw[bi][slot][t][0])[jj];
                    u64 a0 = pack2(pre, 0.f), a1 = 0ull, a2 = 0ull;
                    fma2(a0, wR[0], v0); fma2(a1, wR[1], v1); fma2(a2, wR[2], v2);
                    fma2(a0, wR[3], v3); fma2(a1, wR[4], v4); fma2(a2, wR[5], v5);
                    fma2(a0, wR[6], v6); fma2(a1, wR[7], v7); fma2(a2, wR[8], v8);
                    h = tanh_fast(hsum2(add2(add2(a0, a1), a2)));
                    sts_f32(cur + 4 * jj, h);
                    hp = cur; cur += ROWB;
                }
            } else if (role == 2) {
                u32 hp  = self_base + ((slot ^ 1) * CH + CH - 1) * ROWB;
                u32 cur = self_base + (slot * CH) * ROWB;
                #pragma unroll 4
                for (int t = 0; t < CH; ++t) {
                    u64 v0 = lds_u64(hp),      v1 = lds_u64(hp + 8),  v2 = lds_u64(hp + 16);
                    u64 v3 = lds_u64(hp + 24), v4 = lds_u64(hp + 32), v5 = lds_u64(hp + 40);
                    u64 v6 = lds_u64(hp + 48), v7 = lds_u64(hp + 56), v8 = lds_u64(hp + 64);
                    const u64* pv = &s_h0[bi][slot][t][0];   // producer row (barrier-safe)
                    u64 a0 = binit, a1 = 0ull, a2 = 0ull;
                    fma2(a0, wP[0], pv[0]); fma2(a1, wP[1], pv[1]); fma2(a2, wP[2], pv[2]);
                    fma2(a0, wP[3], pv[3]); fma2(a1, wP[4], pv[4]); fma2(a2, wP[5], pv[5]);
                    fma2(a0, wP[6], pv[6]); fma2(a1, wP[7], pv[7]); fma2(a2, wP[8], pv[8]);
                    fma2(a0, wR[0], v0); fma2(a1, wR[1], v1); fma2(a2, wR[2], v2);
                    fma2(a0, wR[3], v3); fma2(a1, wR[4], v4); fma2(a2, wR[5], v5);
                    fma2(a0, wR[6], v6); fma2(a1, wR[7], v7); fma2(a2, wR[8], v8);
                    h = tanh_fast(hsum2(add2(add2(a0, a1), a2)));
                    sts_f32(cur + 4 * jj, h);
                    hp = cur; cur += ROWB;
                }
            } else { // role 3
                u32 hp  = self_base + ((slot ^ 1) * CH + CH - 1) * ROWB;
                u32 cur = self_base + (slot * CH) * ROWB;
                float* go = g_h2 + ((size_t)b * S_ + t0) * H_;
                #pragma unroll 4
                for (int t = 0; t < CH; ++t) {
                    u64 v0 = lds_u64(hp),      v1 = lds_u64(hp + 8),  v2 = lds_u64(hp + 16);
                    u64 v3 = lds_u64(hp + 24), v4 = lds_u64(hp + 32), v5 = lds_u64(hp + 40);
                    u64 v6 = lds_u64(hp + 48), v7 = lds_u64(hp + 56), v8 = lds_u64(hp + 64);
                    const u64* pv = &s_h1[bi][slot][t][0];
                    u64 a0 = binit, a1 = 0ull, a2 = 0ull;
                    fma2(a0, wP[0], pv[0]); fma2(a1, wP[1], pv[1]); fma2(a2, wP[2], pv[2]);
                    fma2(a0, wP[3], pv[3]); fma2(a1, wP[4], pv[4]); fma2(a2, wP[5], pv[5]);
                    fma2(a0, wP[6], pv[6]); fma2(a1, wP[7], pv[7]); fma2(a2, wP[8], pv[8]);
                    fma2(a0, wR[0], v0); fma2(a1, wR[1], v1); fma2(a2, wR[2], v2);
                    fma2(a0, wR[3], v3); fma2(a1, wR[4], v4); fma2(a2, wR[5], v5);
                    fma2(a0, wR[6], v6); fma2(a1, wR[7], v7); fma2(a2, wR[8], v8);
                    h = tanh_fast(hsum2(add2(add2(a0, a1), a2)));
                    sts_f32(cur + 4 * jj, h);
                    go[t * H_ + jj] = h;                 // off-chain; dup lanes benign
                    hp = cur; cur += ROWB;
                }
            }
        }
        __syncthreads();
    }

    if (write_hidden && role >= 1 && act)
        out[(size_t)B_ * S_ + (size_t)(role - 1) * B_ * H_ + b * H_ + lane] = h;
}

// ---------------------------------------------------------------------------
// Kernel B: MLP head. Coalesced smem staging of 256 rows/block, then
// f32x2-packed per-row compute.
// ---------------------------------------------------------------------------
__global__ __launch_bounds__(256)
void mlp_head_kernel(const float* __restrict__ W1, const float* __restrict__ b1,
                     const float* __restrict__ W2, const float* __restrict__ b2,
                     const float* __restrict__ W3, const float* __restrict__ b3,
                     const float* __restrict__ W4, const float* __restrict__ b4,
                     const float* __restrict__ W5, const float* __restrict__ b5,
                     const float* __restrict__ W6, const float* __restrict__ b6,
                     float* __restrict__ out)
{
    __shared__ u64 sROW[256 * 9];        // 18 KB: 256 rows of 18 floats
    __shared__ u64 sW1[162], sW2[90], sW3[40], sW4[16], sW5[4];
    __shared__ float sb1[18], sb2[10], sb3[8], sb4[4], sb5[2], sW6f[2], sb6f[1];

    const int tid = threadIdx.x;
    if (tid < 162) sW1[tid] = __ldg((const u64*)W1 + tid);
    if (tid < 90)  sW2[tid] = __ldg((const u64*)W2 + tid);
    if (tid < 40)  sW3[tid] = __ldg((const u64*)W3 + tid);
    if (tid < 16)  sW4[tid] = __ldg((const u64*)W4 + tid);
    if (tid < 4)  { sW5[tid] = __ldg((const u64*)W5 + tid); sb4[tid] = b4[tid]; }
    if (tid < 18)  sb1[tid] = b1[tid];
    if (tid < 10)  sb2[tid] = b2[tid];
    if (tid < 8)   sb3[tid] = b3[tid];
    if (tid < 2)  { sb5[tid] = b5[tid]; sW6f[tid] = W6[tid]; }
    if (tid == 0)  sb6f[0] = b6[0];

    // Coalesced stage: this block's 256 rows (2304 u64 contiguous).
    const size_t base = (size_t)blockIdx.x * 256;
    const u64* gh = (const u64*)g_h2 + base * 9;
    #pragma unroll
    for (int i = 0; i < 9; ++i) sROW[tid + i * 256] = __ldg(&gh[tid + i * 256]);
    __syncthreads();

    u64 a0[9];
    #pragma unroll
    for (int m = 0; m < 9; ++m) a0[m] = sROW[tid * 9 + m];   // 2-way conflict LDS.64

    float a1[18];
    #pragma unroll
    for (int j = 0; j < 18; ++j) {
        u64 acc = pack2(sb1[j], 0.f), accb = 0ull;
        #pragma unroll
        for (int m = 0; m < 9; ++m) fma2((m & 1) ? accb : acc, sW1[j * 9 + m], a0[m]);
        a1[j] = fmaxf(hsum2(add2(acc, accb)), 0.f);
    }
    u64 a1p[9];
    #pragma unroll
    for (int m = 0; m < 9; ++m) a1p[m] = pack2(a1[2 * m], a1[2 * m + 1]);

    float a2[10];
    #pragma unroll
    for (int j = 0; j < 10; ++j) {
        u64 acc = pack2(sb2[j], 0.f), accb = 0ull;
        #pragma unroll
        for (int m = 0; m < 9; ++m) fma2((m & 1) ? accb : acc, sW2[j * 9 + m], a1p[m]);
        a2[j] = fmaxf(hsum2(add2(acc, accb)), 0.f);
    }
    u64 a2p[5];
    #pragma unroll
    for (int m = 0; m < 5; ++m) a2p[m] = pack2(a2[2 * m], a2[2 * m + 1]);

    float a3[8];
    #pragma unroll
    for (int j = 0; j < 8; ++j) {
        u64 acc = pack2(sb3[j], 0.f), accb = 0ull;
        #pragma unroll
        for (int m = 0; m < 5; ++m) fma2((m & 1) ? accb : acc, sW3[j * 5 + m], a2p[m]);
        a3[j] = fmaxf(hsum2(add2(acc, accb)), 0.f);
    }
    u64 a3p[4];
    #pragma unroll
    for (int m = 0; m < 4; ++m) a3p[m] = pack2(a3[2 * m], a3[2 * m + 1]);

    float a4[4];
    #pragma unroll
    for (int j = 0; j < 4; ++j) {
        u64 acc = pack2(sb4[j], 0.f), accb = 0ull;
        #pragma unroll
        for (int m = 0; m < 4; ++m) fma2((m & 1) ? accb : acc, sW4[j * 4 + m], a3p[m]);
        a4[j] = fmaxf(hsum2(add2(acc, accb)), 0.f);
    }
    u64 a4p[2] = { pack2(a4[0], a4[1]), pack2(a4[2], a4[3]) };

    float a5[2];
    #pragma unroll
    for (int j = 0; j < 2; ++j) {
        u64 acc = pack2(sb5[j], 0.f);
        fma2(acc, sW5[j * 2 + 0], a4p[0]);
        fma2(acc, sW5[j * 2 + 1], a4p[1]);
        a5[j] = fmaxf(hsum2(acc), 0.f);
    }
    out[base + tid] = fmaf(a5[0], sW6f[0], fmaf(a5[1], sW6f[1], sb6f[0]));
}

// ---------------------------------------------------------------------------
// Launch
// ---------------------------------------------------------------------------
extern "C" void kernel_launch(void* const* d_in, const int* in_sizes, int n_in,
                              void* d_out, int out_size)
{
    const float* input  = (const float*)d_in[0];
    const float* hidden = (const float*)d_in[1];
    const float* Wih0 = (const float*)d_in[2];
    const float* bih0 = (const float*)d_in[3];
    const float* Whh0 = (const float*)d_in[4];
    const float* bhh0 = (const float*)d_in[5];
    const float* Wih1 = (const float*)d_in[6];
    const float* bih1 = (const float*)d_in[7];
    const float* Whh1 = (const float*)d_in[8];
    const float* bhh1 = (const float*)d_in[9];
    const float* Wih2 = (const float*)d_in[10];
    const float* bih2 = (const float*)d_in[11];
    const float* Whh2 = (const float*)d_in[12];
    const float* bhh2 = (const float*)d_in[13];
    const float* W1 = (const float*)d_in[14];
    const float* b1 = (const float*)d_in[15];
    const float* W2 = (const float*)d_in[16];
    const float* b2 = (const float*)d_in[17];
    const float* W3 = (const float*)d_in[18];
    const float* b3 = (const float*)d_in[19];
    const float* W4 = (const float*)d_in[20];
    const float* b4 = (const float*)d_in[21];
    const float* W5 = (const float*)d_in[22];
    const float* b5 = (const float*)d_in[23];
    const float* W6 = (const float*)d_in[24];
    const float* b6 = (const float*)d_in[25];

    float* out = (float*)d_out;
    const int write_hidden = (out_size >= B_ * S_ + 3 * B_ * H_) ? 1 : 0;

    rnn_scan_kernel<<<B_ / 2, 256>>>(input, hidden,
                                     Wih0, bih0, Whh0, bhh0,
                                     Wih1, bih1, Whh1, bhh1,
                                     Wih2, bih2, Whh2, bhh2,
                                     out, write_hidden);

    mlp_head_kernel<<<(B_ * S_) / 256, 256>>>(W1, b1, W2, b2, W3, b3,
                                              W4, b4, W5, b5, W6, b6, out);
}